// round 3
// baseline (speedup 1.0000x reference)
#include <cuda_runtime.h>
#include <cuda_bf16.h>

#define STU_NUM  100000
#define PROB_NUM 20000
#define KNOW_NUM 128
#define DIM      128
#define BATCH    8192
#define HIDDEN   512
#define KOFF     (STU_NUM + PROB_NUM)

// ---------------- intermediate buffers (L2-resident) ----------------
__device__ __align__(16) float g_AC[2 * BATCH * DIM];        // 8 MB
__device__ __align__(16) float g_KT[DIM * KNOW_NUM];         // 64 KB
__device__ __align__(16) float g_P [2 * BATCH * KNOW_NUM];   // 8 MB
__device__ __align__(16) float g_S [BATCH * KNOW_NUM];       // 4 MB
__device__ __align__(16) float g_H1[BATCH * HIDDEN];         // 16 MB
__device__ __align__(16) float g_H2[BATCH * (HIDDEN / 2)];   // 8 MB
__device__ __align__(16) float g_H3[BATCH * (HIDDEN / 4)];   // 4 MB

__device__ __forceinline__ float sigmoidf_(float x) {
    return 1.0f / (1.0f + __expf(-x));
}
// fast tanh: 1 - 2/(e^{2x}+1).  __expf -> MUFU.EX2 path; |err| ~1e-7 rel,
// avoids the ~40-instr software tanhf when --use_fast_math is absent.
__device__ __forceinline__ float tanhf_(float x) {
    return 1.0f - 2.0f / (__expf(2.0f * x) + 1.0f);
}

// ---------------- gather: AC rows 0..8191 = stu*w_stat, 8192.. = exer*w_kdiff --
__global__ __launch_bounds__(256) void gather_kernel(const float* __restrict__ z,
                              const int* __restrict__ sid,
                              const int* __restrict__ eid,
                              const float* __restrict__ w_stat,
                              const float* __restrict__ w_kdiff)
{
    int i = blockIdx.x * blockDim.x + threadIdx.x;   // float4 index, 2*8192*32 total
    int r = i >> 5;
    int c = (i & 31) << 2;
    int row; const float* w;
    if (r < BATCH) { row = sid[r];         w = w_stat;  }
    else           { row = eid[r - BATCH]; w = w_kdiff; }
    float4 v  = *(const float4*)(z + (size_t)row * DIM + c);
    float4 ww = *(const float4*)(w + c);
    v.x *= ww.x; v.y *= ww.y; v.z *= ww.z; v.w *= ww.w;
    *(float4*)(g_AC + (size_t)r * DIM + c) = v;
}

// ---------------- KT[d][k] = z[KOFF+k][d] ----------------
__global__ __launch_bounds__(128) void kt_kernel(const float* __restrict__ z)
{
    int k = blockIdx.x, d = threadIdx.x;
    g_KT[d * KNOW_NUM + k] = z[(size_t)(KOFF + k) * DIM + d];
}

// ---------------- fp32 tiled GEMM body ----------------
// C[M,N] = epi(A[M,K] @ B[K,N] + bias).  M%128==0, N%64==0, K%16==0.
// BM=128, BN=64, BK=16, 128 threads, 8x8 register tile, double-buffered smem.
template <int EPI>   // 0: none, 1: tanh(x + bias[n])
__device__ __forceinline__ void gemm_body(const float* __restrict__ A,
                                          const float* __restrict__ B,
                                          const float* __restrict__ bias,
                                          float* __restrict__ C,
                                          int M, int N, int K)
{
    constexpr int BM = 128, BN = 64, BK = 16;
    __shared__ __align__(16) float As[2][BK][BM];
    __shared__ __align__(16) float Bs[2][BK][BN];

    const int tid = threadIdx.x;
    const int tr  = tid >> 3;   // 0..15 (row group)
    const int tc  = tid & 7;    // 0..7  (col group)
    const int bm  = blockIdx.y * BM;
    const int bn  = blockIdx.x * BN;

    const float* Ab = A + (size_t)bm * K;

    float4 ra[4], rb[2];

    // prologue load tile 0
    #pragma unroll
    for (int j = 0; j < 4; j++) {
        int id = j * 128 + tid;                       // 512 float4 in A tile
        ra[j] = *(const float4*)(Ab + (size_t)(id >> 2) * K + (id & 3) * 4);
    }
    #pragma unroll
    for (int j = 0; j < 2; j++) {
        int id = j * 128 + tid;                       // 256 float4 in B tile
        rb[j] = *(const float4*)(B + (size_t)(id >> 4) * N + bn + (id & 15) * 4);
    }

    float acc[8][8];
    #pragma unroll
    for (int i = 0; i < 8; i++)
        #pragma unroll
        for (int j = 0; j < 8; j++) acc[i][j] = 0.0f;

    int buf = 0;
    #pragma unroll
    for (int j = 0; j < 4; j++) {
        int id = j * 128 + tid; int ar = id >> 2, ac = (id & 3) * 4;
        As[0][ac + 0][ar] = ra[j].x;
        As[0][ac + 1][ar] = ra[j].y;
        As[0][ac + 2][ar] = ra[j].z;
        As[0][ac + 3][ar] = ra[j].w;
    }
    #pragma unroll
    for (int j = 0; j < 2; j++) {
        int id = j * 128 + tid;
        *(float4*)&Bs[0][id >> 4][(id & 15) * 4] = rb[j];
    }
    __syncthreads();

    for (int k0 = 0; k0 < K; k0 += BK) {
        const bool has_next = (k0 + BK) < K;
        if (has_next) {
            const float* An = Ab + (k0 + BK);
            const float* Bn = B + (size_t)(k0 + BK) * N + bn;
            #pragma unroll
            for (int j = 0; j < 4; j++) {
                int id = j * 128 + tid;
                ra[j] = *(const float4*)(An + (size_t)(id >> 2) * K + (id & 3) * 4);
            }
            #pragma unroll
            for (int j = 0; j < 2; j++) {
                int id = j * 128 + tid;
                rb[j] = *(const float4*)(Bn + (size_t)(id >> 4) * N + (id & 15) * 4);
            }
        }

        #pragma unroll
        for (int kk = 0; kk < BK; kk++) {
            float af[8], bf[8];
            *(float4*)&af[0] = *(const float4*)&As[buf][kk][tr * 8];
            *(float4*)&af[4] = *(const float4*)&As[buf][kk][tr * 8 + 4];
            *(float4*)&bf[0] = *(const float4*)&Bs[buf][kk][tc * 8];
            *(float4*)&bf[4] = *(const float4*)&Bs[buf][kk][tc * 8 + 4];
            #pragma unroll
            for (int i = 0; i < 8; i++)
                #pragma unroll
                for (int j = 0; j < 8; j++)
                    acc[i][j] += af[i] * bf[j];
        }

        if (has_next) {
            buf ^= 1;
            #pragma unroll
            for (int j = 0; j < 4; j++) {
                int id = j * 128 + tid; int ar = id >> 2, ac = (id & 3) * 4;
                As[buf][ac + 0][ar] = ra[j].x;
                As[buf][ac + 1][ar] = ra[j].y;
                As[buf][ac + 2][ar] = ra[j].z;
                As[buf][ac + 3][ar] = ra[j].w;
            }
            #pragma unroll
            for (int j = 0; j < 2; j++) {
                int id = j * 128 + tid;
                *(float4*)&Bs[buf][id >> 4][(id & 15) * 4] = rb[j];
            }
            __syncthreads();
        }
    }

    // epilogue
    float bv[8];
    if (EPI == 1) {
        #pragma unroll
        for (int j = 0; j < 8; j++) bv[j] = bias[bn + tc * 8 + j];
    }
    #pragma unroll
    for (int i = 0; i < 8; i++) {
        float* Cr = C + (size_t)(bm + tr * 8 + i) * N + bn + tc * 8;
        float v[8];
        #pragma unroll
        for (int j = 0; j < 8; j++) {
            float x = acc[i][j];
            if (EPI == 1) x = tanhf_(x + bv[j]);
            v[j] = x;
        }
        *(float4*)(Cr)     = *(float4*)&v[0];
        *(float4*)(Cr + 4) = *(float4*)&v[4];
    }
}

// ---------------- GEMM wrappers (globals referenced device-side) ----------------
__global__ __launch_bounds__(128) void gemm0_k()
{   // P = AC @ KT   (16384, 128, 128)
    gemm_body<0>(g_AC, g_KT, nullptr, g_P, 2 * BATCH, KNOW_NUM, DIM);
}
__global__ __launch_bounds__(128) void gemm1_k(const float* __restrict__ W1,
                                               const float* __restrict__ b1)
{   // H1 = tanh(S @ W1 + b1)   (8192, 512, 128)
    gemm_body<1>(g_S, W1, b1, g_H1, BATCH, HIDDEN, DIM);
}
__global__ __launch_bounds__(128) void gemm2_k(const float* __restrict__ W2,
                                               const float* __restrict__ b2)
{   // H2 = tanh(H1 @ W2 + b2)  (8192, 256, 512)
    gemm_body<1>(g_H1, W2, b2, g_H2, BATCH, HIDDEN / 2, HIDDEN);
}
__global__ __launch_bounds__(128) void gemm3_k(const float* __restrict__ W3,
                                               const float* __restrict__ b3)
{   // H3 = tanh(H2 @ W3 + b3)  (8192, 128, 256)
    gemm_body<1>(g_H2, W3, b3, g_H3, BATCH, HIDDEN / 4, HIDDEN / 2);
}

// ---------------- combine: S = kp * (sig(Pa+bs) - sig(Pc+bk)) ----------------
__global__ __launch_bounds__(256) void combine_kernel(const float* __restrict__ kp,
                               const float* __restrict__ bs_p,
                               const float* __restrict__ bk_p)
{
    int i = blockIdx.x * blockDim.x + threadIdx.x;   // float4 index, 8192*32 total
    float bs = *bs_p, bk = *bk_p;
    const float4 pa = *(const float4*)(g_P + (size_t)i * 4);
    const float4 pc = *(const float4*)(g_P + (size_t)BATCH * KNOW_NUM + (size_t)i * 4);
    const float4 k4 = *(const float4*)(kp + (size_t)i * 4);
    float4 o;
    o.x = k4.x * (sigmoidf_(pa.x + bs) - sigmoidf_(pc.x + bk));
    o.y = k4.y * (sigmoidf_(pa.y + bs) - sigmoidf_(pc.y + bk));
    o.z = k4.z * (sigmoidf_(pa.z + bs) - sigmoidf_(pc.z + bk));
    o.w = k4.w * (sigmoidf_(pa.w + bs) - sigmoidf_(pc.w + bk));
    *(float4*)(g_S + (size_t)i * 4) = o;
}

// ---------------- final: out = sigmoid(H3 . W4 + b4), one warp per row --------
__global__ __launch_bounds__(256) void out_kernel(const float* __restrict__ W4,
                           const float* __restrict__ b4,
                           float* __restrict__ out)
{
    int warp = threadIdx.x >> 5, lane = threadIdx.x & 31;
    int r = blockIdx.x * (blockDim.x >> 5) + warp;
    const float4 h = *(const float4*)(g_H3 + (size_t)r * 128 + lane * 4);
    const float4 w = *(const float4*)(W4 + lane * 4);
    float s = h.x * w.x + h.y * w.y + h.z * w.z + h.w * w.w;
    #pragma unroll
    for (int o = 16; o > 0; o >>= 1) s += __shfl_xor_sync(0xFFFFFFFFu, s, o);
    if (lane == 0) out[r] = sigmoidf_(s + b4[0]);
}

// ---------------- launch ----------------
extern "C" void kernel_launch(void* const* d_in, const int* in_sizes, int n_in,
                              void* d_out, int out_size)
{
    const float* z       = (const float*)d_in[0];
    const int*   sid     = (const int*)  d_in[1];
    const int*   eid     = (const int*)  d_in[2];
    const float* kp      = (const float*)d_in[3];
    const float* w_stat  = (const float*)d_in[4];
    const float* b_stat  = (const float*)d_in[5];
    const float* w_kdiff = (const float*)d_in[6];
    const float* b_kdiff = (const float*)d_in[7];
    const float* W1      = (const float*)d_in[8];
    const float* b1      = (const float*)d_in[9];
    const float* W2      = (const float*)d_in[10];
    const float* b2      = (const float*)d_in[11];
    const float* W3      = (const float*)d_in[12];
    const float* b3      = (const float*)d_in[13];
    const float* W4      = (const float*)d_in[14];
    const float* b4      = (const float*)d_in[15];
    float* out = (float*)d_out;

    gather_kernel<<<(2 * BATCH * (DIM / 4)) / 256, 256>>>(z, sid, eid, w_stat, w_kdiff);
    kt_kernel<<<KNOW_NUM, DIM>>>(z);
    gemm0_k<<<dim3(KNOW_NUM / 64, (2 * BATCH) / 128), 128>>>();
    combine_kernel<<<(BATCH * (KNOW_NUM / 4)) / 256, 256>>>(kp, b_stat, b_kdiff);
    gemm1_k<<<dim3(HIDDEN / 64, BATCH / 128), 128>>>(W1, b1);
    gemm2_k<<<dim3((HIDDEN / 2) / 64, BATCH / 128), 128>>>(W2, b2);
    gemm3_k<<<dim3((HIDDEN / 4) / 64, BATCH / 128), 128>>>(W3, b3);
    out_kernel<<<BATCH / 8, 256>>>(W4, b4, out);
}

// round 6
// speedup vs baseline: 3.1112x; 3.1112x over previous
#include <cuda_runtime.h>
#include <cuda_fp16.h>
#include <cstdint>
#include <stdint.h>

#define STU_NUM  100000
#define PROB_NUM 20000
#define KNOW_NUM 128
#define DIM      128
#define BATCH    8192
#define HIDDEN   512
#define KOFF     (STU_NUM + PROB_NUM)

// ---------------- intermediate buffers (L2-resident) ----------------
__device__ __align__(16) __half g_AC[2 * BATCH * DIM];          // 4 MB
__device__ __align__(16) __half g_KT[DIM * KNOW_NUM];           // 32 KB
__device__ __align__(16) float  g_P [2 * BATCH * KNOW_NUM];     // 8 MB (fp32: sigmoid-diff precision)
__device__ __align__(16) __half g_S [BATCH * KNOW_NUM];         // 2 MB
__device__ __align__(16) __half g_H1[BATCH * HIDDEN];           // 8 MB
__device__ __align__(16) __half g_H2[BATCH * (HIDDEN / 2)];     // 4 MB
__device__ __align__(16) __half g_H3[BATCH * (HIDDEN / 4)];     // 2 MB
__device__ __align__(16) __half g_W1h[DIM * HIDDEN];
__device__ __align__(16) __half g_W2h[HIDDEN * (HIDDEN / 2)];
__device__ __align__(16) __half g_W3h[(HIDDEN / 2) * (HIDDEN / 4)];

__device__ __forceinline__ float sigmoidf_(float x) {
    return 1.0f / (1.0f + __expf(-x));
}
// fast tanh: 1 - 2/(e^{2x}+1); saturates correctly at +-1 for large |x|.
__device__ __forceinline__ float tanhf_(float x) {
    return 1.0f - 2.0f / (__expf(2.0f * x) + 1.0f);
}

// ---------------- PTX helpers ----------------
__device__ __forceinline__ uint32_t s2u(const void* p) {
    return (uint32_t)__cvta_generic_to_shared(p);
}
__device__ __forceinline__ void ldmA(uint32_t addr, uint32_t& a0, uint32_t& a1,
                                     uint32_t& a2, uint32_t& a3) {
    asm volatile("ldmatrix.sync.aligned.m8n8.x4.shared.b16 {%0,%1,%2,%3}, [%4];"
                 : "=r"(a0), "=r"(a1), "=r"(a2), "=r"(a3) : "r"(addr));
}
__device__ __forceinline__ void ldmBT(uint32_t addr, uint32_t& b0, uint32_t& b1) {
    asm volatile("ldmatrix.sync.aligned.m8n8.x2.trans.shared.b16 {%0,%1}, [%2];"
                 : "=r"(b0), "=r"(b1) : "r"(addr));
}
__device__ __forceinline__ void mma16816(float* d, uint32_t a0, uint32_t a1,
                                         uint32_t a2, uint32_t a3,
                                         uint32_t b0, uint32_t b1) {
    asm volatile("mma.sync.aligned.m16n8k16.row.col.f32.f16.f16.f32 "
                 "{%0,%1,%2,%3}, {%4,%5,%6,%7}, {%8,%9}, {%0,%1,%2,%3};"
                 : "+f"(d[0]), "+f"(d[1]), "+f"(d[2]), "+f"(d[3])
                 : "r"(a0), "r"(a1), "r"(a2), "r"(a3), "r"(b0), "r"(b1));
}
__device__ __forceinline__ void cpasync16(uint32_t saddr, const void* g) {
    asm volatile("cp.async.cg.shared.global [%0], [%1], 16;" :: "r"(saddr), "l"(g));
}

// ---------------- gather: AC rows 0..8191 = stu*w_stat, 8192.. = exer*w_kdiff --
__global__ __launch_bounds__(256) void gather_kernel(const float* __restrict__ z,
                              const int* __restrict__ sid,
                              const int* __restrict__ eid,
                              const float* __restrict__ w_stat,
                              const float* __restrict__ w_kdiff)
{
    int i = blockIdx.x * blockDim.x + threadIdx.x;   // float4 index, 2*8192*32 total
    int r = i >> 5;
    int c = (i & 31) << 2;
    int row; const float* w;
    if (r < BATCH) { row = sid[r];         w = w_stat;  }
    else           { row = eid[r - BATCH]; w = w_kdiff; }
    float4 v  = *(const float4*)(z + (size_t)row * DIM + c);
    float4 ww = *(const float4*)(w + c);
    __half2* d = (__half2*)(g_AC + (size_t)r * DIM + c);
    d[0] = __floats2half2_rn(v.x * ww.x, v.y * ww.y);
    d[1] = __floats2half2_rn(v.z * ww.z, v.w * ww.w);
}

// ---------------- KT[d][k] = z[KOFF+k][d] (half) ----------------
__global__ __launch_bounds__(128) void kt_kernel(const float* __restrict__ z)
{
    int k = blockIdx.x, d = threadIdx.x;
    g_KT[d * KNOW_NUM + k] = __float2half_rn(z[(size_t)(KOFF + k) * DIM + d]);
}

// ---------------- weight fp32 -> fp16 conversion (single kernel) ----------------
// float4 granularity: W1 16384, W2 32768, W3 8192 -> 57344 total
__global__ __launch_bounds__(256) void prep_weights(const float* __restrict__ W1,
                                                    const float* __restrict__ W2,
                                                    const float* __restrict__ W3)
{
    int i = blockIdx.x * blockDim.x + threadIdx.x;
    const float* src; __half* dst; int off;
    if (i < 16384)      { src = W1; dst = g_W1h; off = i; }
    else if (i < 49152) { src = W2; dst = g_W2h; off = i - 16384; }
    else                { src = W3; dst = g_W3h; off = i - 49152; }
    float4 v = ((const float4*)src)[off];
    __half2* d = (__half2*)(dst + (size_t)off * 4);
    d[0] = __floats2half2_rn(v.x, v.y);
    d[1] = __floats2half2_rn(v.z, v.w);
}

// ---------------- fp16 tensor-core GEMM body ----------------
// C[M,N] = epi(A[M,K]@B[K,N] + bias). BM=128 BN=64 BK=32, 128 thr (2x2 warps,
// 64x32 warp tile), cp.async double-buffered smem, padded LDs -> conflict-free
// ldmatrix. A,B half; C half (OUT_HALF) or float.
template <int EPI_TANH, int OUT_HALF>
__device__ __forceinline__ void hgemm_body(const __half* __restrict__ A,
                                           const __half* __restrict__ B,
                                           const float* __restrict__ bias,
                                           void* __restrict__ Cp,
                                           int M, int N, int K)
{
    constexpr int BM = 128, BN = 64, BK = 32;
    constexpr int LDA = 40, LDB = 72;   // halves; 80B / 144B rows -> distinct 16B banks mod 128B
    __shared__ __align__(16) __half As[2][BM * LDA];
    __shared__ __align__(16) __half Bs[2][BK * LDB];

    const int tid  = threadIdx.x;
    const int lane = tid & 31;
    const int warp = tid >> 5;
    const int wm   = (warp >> 1) * 64;
    const int wn   = (warp & 1) * 32;
    const int bm   = blockIdx.y * BM;
    const int bn   = blockIdx.x * BN;

    auto load_tile = [&](int buf, int k0) {
        #pragma unroll
        for (int j = 0; j < 4; j++) {                  // A: 512 chunks of 8 halves
            int id = j * 128 + tid; int r = id >> 2, c = (id & 3) * 8;
            cpasync16(s2u(&As[buf][r * LDA + c]), A + (size_t)(bm + r) * K + k0 + c);
        }
        #pragma unroll
        for (int j = 0; j < 2; j++) {                  // B: 256 chunks
            int id = j * 128 + tid; int r = id >> 3, c = (id & 7) * 8;
            cpasync16(s2u(&Bs[buf][r * LDB + c]), B + (size_t)(k0 + r) * N + bn + c);
        }
        asm volatile("cp.async.commit_group;");
    };

    float acc[4][4][4];
    #pragma unroll
    for (int mi = 0; mi < 4; mi++)
        #pragma unroll
        for (int ni = 0; ni < 4; ni++)
            #pragma unroll
            for (int q = 0; q < 4; q++) acc[mi][ni][q] = 0.0f;

    load_tile(0, 0);
    asm volatile("cp.async.wait_group 0;");
    __syncthreads();

    int buf = 0;
    for (int k0 = 0; k0 < K; k0 += BK) {
        const bool has_next = (k0 + BK) < K;
        if (has_next) load_tile(buf ^ 1, k0 + BK);

        #pragma unroll
        for (int ks = 0; ks < 2; ks++) {
            uint32_t a[4][4], b[4][2];
            // A frags: lanes 0-15 rows 0-15 @ k-col ks*16, lanes 16-31 same rows @ +8
            const int arow = wm + (lane & 15);
            const int acol = ks * 16 + (lane >> 4) * 8;
            #pragma unroll
            for (int mi = 0; mi < 4; mi++)
                ldmA(s2u(&As[buf][(arow + mi * 16) * LDA + acol]),
                     a[mi][0], a[mi][1], a[mi][2], a[mi][3]);
            // B frags: lanes 0-7 -> k rows 0-7 of kstep, lanes 8-15 -> rows 8-15
            const int brow = ks * 16 + (lane & 7) + ((lane >> 3) & 1) * 8;
            #pragma unroll
            for (int ni = 0; ni < 4; ni++)
                ldmBT(s2u(&Bs[buf][brow * LDB + wn + ni * 8]), b[ni][0], b[ni][1]);
            #pragma unroll
            for (int mi = 0; mi < 4; mi++)
                #pragma unroll
                for (int ni = 0; ni < 4; ni++)
                    mma16816(acc[mi][ni], a[mi][0], a[mi][1], a[mi][2], a[mi][3],
                             b[ni][0], b[ni][1]);
        }

        if (has_next) {
            asm volatile("cp.async.wait_group 0;");
            __syncthreads();
            buf ^= 1;
        }
    }

    // epilogue: thread owns (row, c..c+1) and (row+8, c..c+1) per 16x8 tile
    #pragma unroll
    for (int mi = 0; mi < 4; mi++) {
        const int r0 = bm + wm + mi * 16 + (lane >> 2);
        #pragma unroll
        for (int ni = 0; ni < 4; ni++) {
            const int c = bn + wn + ni * 8 + (lane & 3) * 2;
            float x0 = acc[mi][ni][0], x1 = acc[mi][ni][1];
            float x2 = acc[mi][ni][2], x3 = acc[mi][ni][3];
            if (EPI_TANH) {
                const float bv0 = bias[c], bv1 = bias[c + 1];
                x0 = tanhf_(x0 + bv0); x1 = tanhf_(x1 + bv1);
                x2 = tanhf_(x2 + bv0); x3 = tanhf_(x3 + bv1);
            }
            if (OUT_HALF) {
                __half* C = (__half*)Cp;
                *(__half2*)(C + (size_t)r0 * N + c)       = __floats2half2_rn(x0, x1);
                *(__half2*)(C + (size_t)(r0 + 8) * N + c) = __floats2half2_rn(x2, x3);
            } else {
                float* C = (float*)Cp;
                *(float2*)(C + (size_t)r0 * N + c)        = make_float2(x0, x1);
                *(float2*)(C + (size_t)(r0 + 8) * N + c)  = make_float2(x2, x3);
            }
        }
    }
}

// ---------------- GEMM wrappers ----------------
__global__ __launch_bounds__(128) void gemm0_k()
{   // P = AC @ KT   (16384, 128, 128), fp32 out
    hgemm_body<0, 0>(g_AC, g_KT, nullptr, g_P, 2 * BATCH, KNOW_NUM, DIM);
}
__global__ __launch_bounds__(128) void gemm1_k(const float* __restrict__ b1)
{   // H1 = tanh(S @ W1 + b1)   (8192, 512, 128)
    hgemm_body<1, 1>(g_S, g_W1h, b1, g_H1, BATCH, HIDDEN, DIM);
}
__global__ __launch_bounds__(128) void gemm2_k(const float* __restrict__ b2)
{   // H2 = tanh(H1 @ W2 + b2)  (8192, 256, 512)
    hgemm_body<1, 1>(g_H1, g_W2h, b2, g_H2, BATCH, HIDDEN / 2, HIDDEN);
}
__global__ __launch_bounds__(128) void gemm3_k(const float* __restrict__ b3)
{   // H3 = tanh(H2 @ W3 + b3)  (8192, 128, 256)
    hgemm_body<1, 1>(g_H2, g_W3h, b3, g_H3, BATCH, HIDDEN / 4, HIDDEN / 2);
}

// ---------------- combine: S = kp * (sig(Pa+bs) - sig(Pc+bk)) -> half --------
__global__ __launch_bounds__(256) void combine_kernel(const float* __restrict__ kp,
                               const float* __restrict__ bs_p,
                               const float* __restrict__ bk_p)
{
    int i = blockIdx.x * blockDim.x + threadIdx.x;   // float4 index, 8192*32 total
    float bs = *bs_p, bk = *bk_p;
    const float4 pa = *(const float4*)(g_P + (size_t)i * 4);
    const float4 pc = *(const float4*)(g_P + (size_t)BATCH * KNOW_NUM + (size_t)i * 4);
    const float4 k4 = *(const float4*)(kp + (size_t)i * 4);
    float s0 = k4.x * (sigmoidf_(pa.x + bs) - sigmoidf_(pc.x + bk));
    float s1 = k4.y * (sigmoidf_(pa.y + bs) - sigmoidf_(pc.y + bk));
    float s2 = k4.z * (sigmoidf_(pa.z + bs) - sigmoidf_(pc.z + bk));
    float s3 = k4.w * (sigmoidf_(pa.w + bs) - sigmoidf_(pc.w + bk));
    __half2* d = (__half2*)(g_S + (size_t)i * 4);
    d[0] = __floats2half2_rn(s0, s1);
    d[1] = __floats2half2_rn(s2, s3);
}

// ---------------- final: out = sigmoid(H3 . W4 + b4), one warp per row --------
__global__ __launch_bounds__(256) void out_kernel(const float* __restrict__ W4,
                           const float* __restrict__ b4,
                           float* __restrict__ out)
{
    int warp = threadIdx.x >> 5, lane = threadIdx.x & 31;
    int r = blockIdx.x * (blockDim.x >> 5) + warp;
    const __half2* h2 = (const __half2*)(g_H3 + (size_t)r * 128 + lane * 4);
    float2 ha = __half22float2(h2[0]);
    float2 hb = __half22float2(h2[1]);
    const float4 w = *(const float4*)(W4 + lane * 4);
    float s = ha.x * w.x + ha.y * w.y + hb.x * w.z + hb.y * w.w;
    #pragma unroll
    for (int o = 16; o > 0; o >>= 1) s += __shfl_xor_sync(0xFFFFFFFFu, s, o);
    if (lane == 0) out[r] = sigmoidf_(s + b4[0]);
}

// ---------------- launch ----------------
extern "C" void kernel_launch(void* const* d_in, const int* in_sizes, int n_in,
                              void* d_out, int out_size)
{
    const float* z       = (const float*)d_in[0];
    const int*   sid     = (const int*)  d_in[1];
    const int*   eid     = (const int*)  d_in[2];
    const float* kp      = (const float*)d_in[3];
    const float* w_stat  = (const float*)d_in[4];
    const float* b_stat  = (const float*)d_in[5];
    const float* w_kdiff = (const float*)d_in[6];
    const float* b_kdiff = (const float*)d_in[7];
    const float* W1      = (const float*)d_in[8];
    const float* b1      = (const float*)d_in[9];
    const float* W2      = (const float*)d_in[10];
    const float* b2      = (const float*)d_in[11];
    const float* W3      = (const float*)d_in[12];
    const float* b3      = (const float*)d_in[13];
    const float* W4      = (const float*)d_in[14];
    const float* b4      = (const float*)d_in[15];
    float* out = (float*)d_out;

    gather_kernel<<<(2 * BATCH * (DIM / 4)) / 256, 256>>>(z, sid, eid, w_stat, w_kdiff);
    kt_kernel<<<KNOW_NUM, DIM>>>(z);
    prep_weights<<<57344 / 256, 256>>>(W1, W2, W3);
    gemm0_k<<<dim3(KNOW_NUM / 64, (2 * BATCH) / 128), 128>>>();
    combine_kernel<<<(BATCH * (KNOW_NUM / 4)) / 256, 256>>>(kp, b_stat, b_kdiff);
    gemm1_k<<<dim3(HIDDEN / 64, BATCH / 128), 128>>>(b1);
    gemm2_k<<<dim3((HIDDEN / 2) / 64, BATCH / 128), 128>>>(b2);
    gemm3_k<<<dim3((HIDDEN / 4) / 64, BATCH / 128), 128>>>(b3);
    out_kernel<<<BATCH / 8, 256>>>(W4, b4, out);
}